// round 16
// baseline (speedup 1.0000x reference)
#include <cuda_runtime.h>
#include <cstddef>

#define HD 128
#define MSGCAP 250000

// ---------------- scratch (device globals; no allocation allowed) ----------
__device__ float g_hcol [500000 * 128];
__device__ float g_hfilt[250000 * 128];
__device__ float g_hpred[100000 * 128];
__device__ float g_hscan[ 50000 * 128];
__device__ float g_hjoin[ 25000 * 128];
__device__ float g_henc [ 16384 * 128];
__device__ float g_msg  [MSGCAP * 128];
__device__ float g_w1r  [5 * 256 * 128];   // tf32-rounded W1 per level
__device__ float g_w2r  [5 * 128 * 128];   // tf32-rounded W2 per level

// ---------------- helpers --------------------------------------------------
__device__ __forceinline__ unsigned tf32u(float x) {
    unsigned r;
    asm("cvt.rna.tf32.f32 %0, %1;" : "=r"(r) : "f"(x));
    return r;
}
__device__ __forceinline__ float tf32f(float x) {
    return __uint_as_float(tf32u(x));
}
__device__ __forceinline__ void mma8(float (&c)[4],
                                     unsigned a0, unsigned a1, unsigned a2, unsigned a3,
                                     unsigned b0, unsigned b1) {
    asm("mma.sync.aligned.m16n8k8.row.col.f32.tf32.tf32.f32 "
        "{%0,%1,%2,%3}, {%4,%5,%6,%7}, {%8,%9}, {%0,%1,%2,%3};"
        : "+f"(c[0]), "+f"(c[1]), "+f"(c[2]), "+f"(c[3])
        : "r"(a0), "r"(a1), "r"(a2), "r"(a3), "r"(b0), "r"(b1));
}
#define CP_ASYNC16(dst_u32, src_ptr) \
    asm volatile("cp.async.ca.shared.global [%0], [%1], 16;" \
                 :: "r"(dst_u32), "l"(src_ptr))
#define CP_COMMIT()  asm volatile("cp.async.commit_group;")
#define CP_WAIT0()   asm volatile("cp.async.wait_group 0;")

// ---- prep: tf32-round W1 (5x256x128) and W2 (5x128x128) -------------------
__global__ void w_prep_kernel(const float* __restrict__ W1,
                              const float* __restrict__ W2) {
    int i = blockIdx.x * blockDim.x + threadIdx.x;
    if (i < 5 * 256 * 128) g_w1r[i] = tf32f(W1[i]);
    if (i < 5 * 128 * 128) g_w2r[i] = tf32f(W2[i]);
}

// ============ encoder: 256 thr, 8 warps; warp = 16 rows x 64 cols ==========
#define EWST 136

__device__ __forceinline__ void enc_body(
    const float* __restrict__ x, const float* __restrict__ W,
    const float* __restrict__ b, float* __restrict__ out, int N,
    int bid, int nb, float* Wh, float* Wl)
{
    int t    = threadIdx.x;
    int w    = t >> 5;
    int lane = t & 31;
    int g    = lane >> 2;
    int tg   = lane & 3;
    int rowg = w & 3;
    int c0   = (w >> 2) * 64;

#pragma unroll
    for (int u = 0; u < 4; u++) {
        int fi = u * 256 + t;
        int k = fi >> 5, n0 = (fi & 31) * 4;
        float4 v = *(const float4*)(W + (size_t)k * HD + n0);
        float4 h, l;
        h.x = tf32f(v.x); l.x = tf32f(v.x - h.x);
        h.y = tf32f(v.y); l.y = tf32f(v.y - h.y);
        h.z = tf32f(v.z); l.z = tf32f(v.z - h.z);
        h.w = tf32f(v.w); l.w = tf32f(v.w - h.w);
        *(float4*)(Wh + k * EWST + n0) = h;
        *(float4*)(Wl + k * EWST + n0) = l;
    }
    __syncthreads();

    int ntiles = (N + 63) / 64;
    for (int tile = bid; tile < ntiles; tile += nb) {
        int r0 = tile * 64 + rowg * 16 + g;
        int r1 = r0 + 8;
        const float* xr0 = x + (size_t)r0 * 32 + tg;
        const float* xr1 = x + (size_t)r1 * 32 + tg;
        bool v0 = r0 < N, v1 = r1 < N;

        float a0f[8], a1f[8];
#pragma unroll
        for (int q = 0; q < 8; q++) {
            a0f[q] = v0 ? xr0[q * 4] : 0.f;
            a1f[q] = v1 ? xr1[q * 4] : 0.f;
        }
        unsigned ah0[8], al0[8], ah1[8], al1[8];
#pragma unroll
        for (int q = 0; q < 8; q++) {
            float h0 = tf32f(a0f[q]); ah0[q] = __float_as_uint(h0);
            al0[q] = tf32u(a0f[q] - h0);
            float h1 = tf32f(a1f[q]); ah1[q] = __float_as_uint(h1);
            al1[q] = tf32u(a1f[q] - h1);
        }

        float acc[8][4];
#pragma unroll
        for (int j = 0; j < 8; j++)
#pragma unroll
            for (int q = 0; q < 4; q++) acc[j][q] = 0.f;

#pragma unroll
        for (int kt = 0; kt < 4; kt++) {
            int k0 = kt * 8;
            const float* wh0 = Wh + (k0 + tg) * EWST + c0 + g;
            const float* wh1 = wh0 + 4 * EWST;
            const float* wl0 = Wl + (k0 + tg) * EWST + c0 + g;
            const float* wl1 = wl0 + 4 * EWST;
            unsigned A0h = ah0[kt * 2], A2h = ah0[kt * 2 + 1];
            unsigned A1h = ah1[kt * 2], A3h = ah1[kt * 2 + 1];
            unsigned A0l = al0[kt * 2], A2l = al0[kt * 2 + 1];
            unsigned A1l = al1[kt * 2], A3l = al1[kt * 2 + 1];
#pragma unroll
            for (int j = 0; j < 8; j++) {
                unsigned bh0 = __float_as_uint(wh0[8 * j]);
                unsigned bh1 = __float_as_uint(wh1[8 * j]);
                unsigned bl0 = __float_as_uint(wl0[8 * j]);
                unsigned bl1 = __float_as_uint(wl1[8 * j]);
                mma8(acc[j], A0l, A1l, A2l, A3l, bh0, bh1);
                mma8(acc[j], A0h, A1h, A2h, A3h, bl0, bl1);
                mma8(acc[j], A0h, A1h, A2h, A3h, bh0, bh1);
            }
        }

#pragma unroll
        for (int j = 0; j < 8; j++) {
            int col = c0 + 8 * j + 2 * tg;
            float2 bb = *(const float2*)(b + col);
            if (v0) {
                float2 o;
                o.x = fmaxf(acc[j][0] + bb.x, 0.f);
                o.y = fmaxf(acc[j][1] + bb.y, 0.f);
                *(float2*)(out + (size_t)r0 * HD + col) = o;
            }
            if (v1) {
                float2 o;
                o.x = fmaxf(acc[j][2] + bb.x, 0.f);
                o.y = fmaxf(acc[j][3] + bb.y, 0.f);
                *(float2*)(out + (size_t)r1 * HD + col) = o;
            }
        }
    }
}

__global__ __launch_bounds__(256) void enc_mma_kernel(
    const float* __restrict__ x, const float* __restrict__ W,
    const float* __restrict__ b, float* __restrict__ out, int N)
{
    __shared__ float Wh[32 * EWST];
    __shared__ float Wl[32 * EWST];
    enc_body(x, W, b, out, N, blockIdx.x, gridDim.x, Wh, Wl);
}

// paired encoder: blocks [0,g0) do type A, [g0,g0+g1) do type B
__global__ __launch_bounds__(256) void enc_mma_pair_kernel(
    const float* xA, const float* WA, const float* bA, float* oA, int NA, int g0,
    const float* xB, const float* WB_, const float* bB, float* oB, int NB)
{
    __shared__ float Wh[32 * EWST];
    __shared__ float Wl[32 * EWST];
    if ((int)blockIdx.x < g0)
        enc_body(xA, WA, bA, oA, NA, blockIdx.x, g0, Wh, Wl);
    else
        enc_body(xB, WB_, bB, oB, NB, blockIdx.x - g0, gridDim.x - g0, Wh, Wl);
}

// ---------------- edge scatter: msg[dst[e]] += h_src[src[e]] ---------------
#define EPW 4
__global__ __launch_bounds__(256) void scatter_kernel(
    const float* __restrict__ h_src, const int* __restrict__ src,
    const int* __restrict__ dst, float* __restrict__ msg, int E)
{
    int wid = blockIdx.x * (blockDim.x >> 5) + (threadIdx.x >> 5);
    int lane = threadIdx.x & 31;
    int e0 = wid * EPW;
    if (e0 >= E) return;

    int4 s4, d4;
    if (e0 + EPW <= E) {
        s4 = *(const int4*)(src + e0);
        d4 = *(const int4*)(dst + e0);
    } else {
        s4.x = src[e0];
        s4.y = (e0 + 1 < E) ? src[e0 + 1] : -1;
        s4.z = (e0 + 2 < E) ? src[e0 + 2] : -1;
        s4.w = (e0 + 3 < E) ? src[e0 + 3] : -1;
        d4.x = dst[e0];
        d4.y = (e0 + 1 < E) ? dst[e0 + 1] : 0;
        d4.z = (e0 + 2 < E) ? dst[e0 + 2] : 0;
        d4.w = (e0 + 3 < E) ? dst[e0 + 3] : 0;
    }
    int sidx[EPW] = { s4.x, s4.y, s4.z, s4.w };
    int didx[EPW] = { d4.x, d4.y, d4.z, d4.w };

    float4 v[EPW];
#pragma unroll
    for (int i = 0; i < EPW; i++)
        if (sidx[i] >= 0)
            v[i] = *(const float4*)(h_src + (size_t)sidx[i] * HD + lane * 4);
#pragma unroll
    for (int i = 0; i < EPW; i++)
        if (sidx[i] >= 0)
            atomicAdd((float4*)(msg + (size_t)didx[i] * HD + lane * 4), v[i]);
}

// ------- tree MLP (R12 structure) + cp.async W staging ---------------------
// 256 thr, 8 warps: rowg = w&3 (16 rows), colh = w>>2 (64 cols). 64 nodes.
// W chunks (32 rows, pre-rounded in g_w1r/g_w2r) double-buffered via cp.async.
#define TPA   260
#define WST   136
#define WCHUNK_F (32 * WST)
#define MLP_SMEM ((64 * TPA + 2 * WCHUNK_F) * sizeof(float))

__device__ __forceinline__ void stage_async(float* wb, const float* __restrict__ Wr,
                                            int krow0, int t) {
    unsigned dst = (unsigned)__cvta_generic_to_shared(wb);
#pragma unroll
    for (int u = 0; u < 4; u++) {
        int fi = u * 256 + t;
        int k = fi >> 5;
        int n0 = (fi & 31) * 4;
        CP_ASYNC16(dst + (unsigned)(k * WST + n0) * 4,
                   Wr + (size_t)(krow0 + k) * HD + n0);
    }
}

__global__ __launch_bounds__(256) void tree_mlp_mma(
    float* __restrict__ h_dst, float* __restrict__ msg,
    const float* __restrict__ W1r, const float* __restrict__ b1,
    const float* __restrict__ W2r, const float* __restrict__ b2, int N)
{
    extern __shared__ float s[];
    float* A  = s;                       // [64][TPA]
    float* WB = s + 64 * TPA;            // [2][32][WST]

    int t    = threadIdx.x;
    int base = blockIdx.x * 64;
    int w    = t >> 5;
    int lane = t & 31;
    int g    = lane >> 2;
    int tg   = lane & 3;
    int rowg = w & 3;
    int c0   = (w >> 2) * 64;
    int m0   = rowg * 16;

    // stage A = tf32(concat(h_dst, msg))
    for (int i = t; i < 64 * 64; i += 256) {
        int n = i >> 6, q = i & 63;
        int f0 = q * 4;
        float4 v = make_float4(0.f, 0.f, 0.f, 0.f);
        if (base + n < N) {
            if (q < 32) v = *(const float4*)(h_dst + (size_t)(base + n) * HD + f0);
            else        v = *(const float4*)(msg   + (size_t)(base + n) * HD + (f0 - 128));
        }
        v.x = tf32f(v.x); v.y = tf32f(v.y); v.z = tf32f(v.z); v.w = tf32f(v.w);
        *(float4*)(A + n * TPA + f0) = v;
    }
    stage_async(WB, W1r, 0, t);
    CP_COMMIT();
    __syncthreads();          // A visible to all; all staging reads of msg done

    // re-zero consumed msg rows (after barrier: no thread still reads msg)
    {
        float4 z4 = make_float4(0.f, 0.f, 0.f, 0.f);
        for (int i = t; i < 64 * 32; i += 256) {
            int n = i >> 5, q = i & 31;
            if (base + n < N)
                *(float4*)(msg + (size_t)(base + n) * HD + q * 4) = z4;
        }
    }

    float acc[8][4];
#pragma unroll
    for (int j = 0; j < 8; j++)
#pragma unroll
        for (int q = 0; q < 4; q++) acc[j][q] = 0.f;

    const float* arow0 = A + (m0 + g) * TPA + tg;
    const float* arow1 = arow0 + 8 * TPA;

    // ---- layer 1: 8 chunks of 32 K-rows (K=256) ----
    for (int c = 0; c < 8; c++) {
        CP_WAIT0();           // chunk c landed (own copies)
        __syncthreads();      // block-wide visibility; other buffer now free
        if (c + 1 < 8) {
            stage_async(WB + ((c + 1) & 1) * WCHUNK_F, W1r, (c + 1) * 32, t);
            CP_COMMIT();      // flight overlaps compute below
        }
        const float* wb = WB + (c & 1) * WCHUNK_F;
#pragma unroll
        for (int kt = 0; kt < 4; kt++) {
            int k0 = c * 32 + kt * 8;
            unsigned a0 = __float_as_uint(arow0[k0]);
            unsigned a1 = __float_as_uint(arow1[k0]);
            unsigned a2 = __float_as_uint(arow0[k0 + 4]);
            unsigned a3 = __float_as_uint(arow1[k0 + 4]);
            const float* wrow0 = wb + (kt * 8 + tg) * WST + c0 + g;
            const float* wrow1 = wrow0 + 4 * WST;
#pragma unroll
            for (int j = 0; j < 8; j++) {
                unsigned b0 = __float_as_uint(wrow0[8 * j]);
                unsigned b1v = __float_as_uint(wrow1[8 * j]);
                mma8(acc[j], a0, a1, a2, a3, b0, b1v);
            }
        }
    }
    __syncthreads();          // all layer-1 reads of A done before Z overwrite

    // ---- bias + relu + write Z (tf32) into A cols [0,128) ----
    {
        float* zr0 = A + (m0 + g) * TPA;
        float* zr1 = zr0 + 8 * TPA;
#pragma unroll
        for (int j = 0; j < 8; j++) {
            int col = c0 + 8 * j + 2 * tg;
            float2 bb = *(const float2*)(b1 + col);
            float2 z0, z1;
            z0.x = tf32f(fmaxf(acc[j][0] + bb.x, 0.f));
            z0.y = tf32f(fmaxf(acc[j][1] + bb.y, 0.f));
            z1.x = tf32f(fmaxf(acc[j][2] + bb.x, 0.f));
            z1.y = tf32f(fmaxf(acc[j][3] + bb.y, 0.f));
            *(float2*)(zr0 + col) = z0;
            *(float2*)(zr1 + col) = z1;
            acc[j][0] = acc[j][1] = acc[j][2] = acc[j][3] = 0.f;
        }
    }
    stage_async(WB, W2r, 0, t);
    CP_COMMIT();

    // ---- layer 2: 4 chunks of 32 K-rows (K=128) ----
    for (int c = 0; c < 4; c++) {
        CP_WAIT0();
        __syncthreads();      // also orders Z writes before first compute
        if (c + 1 < 4) {
            stage_async(WB + ((c + 1) & 1) * WCHUNK_F, W2r, (c + 1) * 32, t);
            CP_COMMIT();
        }
        const float* wb = WB + (c & 1) * WCHUNK_F;
#pragma unroll
        for (int kt = 0; kt < 4; kt++) {
            int k0 = c * 32 + kt * 8;
            unsigned a0 = __float_as_uint(arow0[k0]);
            unsigned a1 = __float_as_uint(arow1[k0]);
            unsigned a2 = __float_as_uint(arow0[k0 + 4]);
            unsigned a3 = __float_as_uint(arow1[k0 + 4]);
            const float* wrow0 = wb + (kt * 8 + tg) * WST + c0 + g;
            const float* wrow1 = wrow0 + 4 * WST;
#pragma unroll
            for (int j = 0; j < 8; j++) {
                unsigned b0 = __float_as_uint(wrow0[8 * j]);
                unsigned b1v = __float_as_uint(wrow1[8 * j]);
                mma8(acc[j], a0, a1, a2, a3, b0, b1v);
            }
        }
    }

    // ---- bias + relu + store to gmem ----
    {
        int n0g = base + m0 + g;
        int n1g = n0g + 8;
#pragma unroll
        for (int j = 0; j < 8; j++) {
            int col = c0 + 8 * j + 2 * tg;
            float2 bb = *(const float2*)(b2 + col);
            if (n0g < N) {
                float2 o;
                o.x = fmaxf(acc[j][0] + bb.x, 0.f);
                o.y = fmaxf(acc[j][1] + bb.y, 0.f);
                *(float2*)(h_dst + (size_t)n0g * HD + col) = o;
            }
            if (n1g < N) {
                float2 o;
                o.x = fmaxf(acc[j][2] + bb.x, 0.f);
                o.y = fmaxf(acc[j][3] + bb.y, 0.f);
                *(float2*)(h_dst + (size_t)n1g * HD + col) = o;
            }
        }
    }
}

// ------- head: out[n] = relu(h @ Wf1 + bf1) @ Wf2 + bf2 --------------------
__global__ __launch_bounds__(128) void final_kernel(
    const float* __restrict__ h, const float* __restrict__ Wf1,
    const float* __restrict__ bf1, const float* __restrict__ Wf2,
    const float* __restrict__ bf2, float* __restrict__ out, int N)
{
    const int BN = 16;
    __shared__ float s_in[BN][128];
    __shared__ float s_z[BN][129];
    int base = blockIdx.x * BN;
    int t = threadIdx.x;

    for (int i = t; i < BN * 32; i += 128) {
        int n = i >> 5, c4 = (i & 31) * 4;
        float4 a = make_float4(0.f, 0.f, 0.f, 0.f);
        if (base + n < N) a = *(const float4*)(h + (size_t)(base + n) * HD + c4);
        *(float4*)&s_in[n][c4] = a;
    }
    __syncthreads();

    float acc[BN];
    float bb = bf1[t];
#pragma unroll
    for (int n = 0; n < BN; n++) acc[n] = bb;
#pragma unroll 4
    for (int k0 = 0; k0 < 128; k0 += 4) {
        float w0 = Wf1[(k0 + 0) * HD + t];
        float w1 = Wf1[(k0 + 1) * HD + t];
        float w2 = Wf1[(k0 + 2) * HD + t];
        float w3 = Wf1[(k0 + 3) * HD + t];
#pragma unroll
        for (int n = 0; n < BN; n++) {
            float4 sv = *(const float4*)&s_in[n][k0];
            acc[n] = fmaf(sv.x, w0, acc[n]);
            acc[n] = fmaf(sv.y, w1, acc[n]);
            acc[n] = fmaf(sv.z, w2, acc[n]);
            acc[n] = fmaf(sv.w, w3, acc[n]);
        }
    }
#pragma unroll
    for (int n = 0; n < BN; n++) s_z[n][t] = fmaxf(acc[n], 0.f);
    __syncthreads();

    if (t < BN && base + t < N) {
        float a = bf2[0];
#pragma unroll 4
        for (int k = 0; k < 128; k++) a = fmaf(s_z[t][k], Wf2[k], a);
        out[base + t] = a;
    }
}

// ---------------------------------------------------------------------------
extern "C" void kernel_launch(void* const* d_in, const int* in_sizes, int n_in,
                              void* d_out, int out_size)
{
    const float* xs[6] = {
        (const float*)d_in[0], (const float*)d_in[1], (const float*)d_in[2],
        (const float*)d_in[3], (const float*)d_in[4], (const float*)d_in[5]
    };
    const float* W_enc = (const float*)d_in[6];
    const float* b_enc = (const float*)d_in[7];
    const float* W1    = (const float*)d_in[8];
    const float* b1    = (const float*)d_in[9];
    const float* W2    = (const float*)d_in[10];
    const float* b2    = (const float*)d_in[11];
    const float* Wf1   = (const float*)d_in[12];
    const float* bf1   = (const float*)d_in[13];
    const float* Wf2   = (const float*)d_in[14];
    const float* bf2   = (const float*)d_in[15];
    const int* esrc[5] = { (const int*)d_in[16], (const int*)d_in[18],
                           (const int*)d_in[20], (const int*)d_in[22],
                           (const int*)d_in[24] };
    const int* edst[5] = { (const int*)d_in[17], (const int*)d_in[19],
                           (const int*)d_in[21], (const int*)d_in[23],
                           (const int*)d_in[25] };
    int E[5] = { in_sizes[16], in_sizes[18], in_sizes[20], in_sizes[22], in_sizes[24] };
    int Nn[6];
    for (int i = 0; i < 6; i++) Nn[i] = in_sizes[i] / 32;

    float *hb[6], *msg, *w1r, *w2r;
    cudaGetSymbolAddress((void**)&hb[0], g_hcol);
    cudaGetSymbolAddress((void**)&hb[1], g_hfilt);
    cudaGetSymbolAddress((void**)&hb[2], g_hpred);
    cudaGetSymbolAddress((void**)&hb[3], g_hscan);
    cudaGetSymbolAddress((void**)&hb[4], g_hjoin);
    cudaGetSymbolAddress((void**)&hb[5], g_henc);
    cudaGetSymbolAddress((void**)&msg,   g_msg);
    cudaGetSymbolAddress((void**)&w1r,   g_w1r);
    cudaGetSymbolAddress((void**)&w2r,   g_w2r);

    cudaFuncSetAttribute(tree_mlp_mma,
                         cudaFuncAttributeMaxDynamicSharedMemorySize, (int)MLP_SMEM);

    cudaMemsetAsync(msg, 0, (size_t)MSGCAP * HD * sizeof(float));

    auto scat = [&](int l) {
        int nwarp = (E[l] + EPW - 1) / EPW;
        int sgrid = (nwarp + 7) / 8;
        scatter_kernel<<<sgrid, 256>>>(hb[l], esrc[l], edst[l], msg, E[l]);
    };
    auto mlp = [&](int l) {
        int Ndst = Nn[l + 1];
        int mgrid = (Ndst + 63) / 64;
        tree_mlp_mma<<<mgrid, 256, MLP_SMEM>>>(hb[l + 1], msg,
                                        w1r + (size_t)l * 256 * HD, b1 + (size_t)l * HD,
                                        w2r + (size_t)l * HD * HD,  b2 + (size_t)l * HD,
                                        Ndst);
    };
    auto enc = [&](int i) {
        int ntiles = (Nn[i] + 63) / 64;
        int grid = ntiles < 296 ? ntiles : 296;
        enc_mma_kernel<<<grid, 256>>>(xs[i], W_enc + (size_t)i * 32 * HD,
                                      b_enc + (size_t)i * HD, hb[i], Nn[i]);
    };

    // kernel launch order (ncu profiles 4th kernel = mlp0):
    w_prep_kernel<<<640, 256>>>(W1, W2);                     // 1
    {   // 2: paired encoder for types 0 and 1
        int t0 = (Nn[0] + 63) / 64; int g0 = t0 < 296 ? t0 : 296;
        int t1 = (Nn[1] + 63) / 64; int g1 = t1 < 296 ? t1 : 296;
        enc_mma_pair_kernel<<<g0 + g1, 256>>>(
            xs[0], W_enc + 0 * 32 * HD, b_enc + 0 * HD, hb[0], Nn[0], g0,
            xs[1], W_enc + 1 * 32 * HD, b_enc + 1 * HD, hb[1], Nn[1]);
    }
    scat(0);           // 3  (needs enc0)
    mlp(0);            // 4  <- profiled (needs enc1 + scat0 + prep)
    enc(2);            // 5
    scat(1);           // 6  (needs mlp0)
    mlp(1);            // 7
    enc(3);            // 8
    scat(2);           // 9
    mlp(2);            // 10
    enc(4);            // 11
    scat(3);           // 12
    mlp(3);            // 13
    enc(5);            // 14
    scat(4);           // 15
    mlp(4);            // 16

    {
        int grid = (Nn[5] + 15) / 16;
        final_kernel<<<grid, 128>>>(hb[5], Wf1, bf1, Wf2, bf2, (float*)d_out, Nn[5]);
    }
}

// round 17
// speedup vs baseline: 1.0205x; 1.0205x over previous
#include <cuda_runtime.h>
#include <cstddef>

#define HD 128
#define MSGCAP 250000

// ---------------- scratch (device globals; no allocation allowed) ----------
__device__ float g_hcol [500000 * 128];
__device__ float g_hfilt[250000 * 128];
__device__ float g_hpred[100000 * 128];
__device__ float g_hscan[ 50000 * 128];
__device__ float g_hjoin[ 25000 * 128];
__device__ float g_henc [ 16384 * 128];
__device__ float g_msg  [MSGCAP * 128];
__device__ float g_w1r  [5 * 256 * 128];   // tf32-rounded W1 per level
__device__ float g_w2r  [5 * 128 * 128];   // tf32-rounded W2 per level

// ---------------- helpers --------------------------------------------------
__device__ __forceinline__ unsigned tf32u(float x) {
    unsigned r;
    asm("cvt.rna.tf32.f32 %0, %1;" : "=r"(r) : "f"(x));
    return r;
}
__device__ __forceinline__ float tf32f(float x) {
    return __uint_as_float(tf32u(x));
}
__device__ __forceinline__ void mma8(float (&c)[4],
                                     unsigned a0, unsigned a1, unsigned a2, unsigned a3,
                                     unsigned b0, unsigned b1) {
    asm("mma.sync.aligned.m16n8k8.row.col.f32.tf32.tf32.f32 "
        "{%0,%1,%2,%3}, {%4,%5,%6,%7}, {%8,%9}, {%0,%1,%2,%3};"
        : "+f"(c[0]), "+f"(c[1]), "+f"(c[2]), "+f"(c[3])
        : "r"(a0), "r"(a1), "r"(a2), "r"(a3), "r"(b0), "r"(b1));
}
#define CP_ASYNC16(dst_u32, src_ptr) \
    asm volatile("cp.async.ca.shared.global [%0], [%1], 16;" \
                 :: "r"(dst_u32), "l"(src_ptr))
#define CP_COMMIT()  asm volatile("cp.async.commit_group;")
#define CP_WAIT0()   asm volatile("cp.async.wait_group 0;")

// ---- prep: tf32-round W1 (5x256x128) and W2 (5x128x128) -------------------
__global__ void w_prep_kernel(const float* __restrict__ W1,
                              const float* __restrict__ W2) {
    int i = blockIdx.x * blockDim.x + threadIdx.x;
    if (i < 5 * 256 * 128) g_w1r[i] = tf32f(W1[i]);
    if (i < 5 * 128 * 128) g_w2r[i] = tf32f(W2[i]);
}

// ============ encoder: 256 thr, 8 warps; warp = 16 rows x 64 cols ==========
#define EWST 136

__device__ __forceinline__ void enc_body(
    const float* __restrict__ x, const float* __restrict__ W,
    const float* __restrict__ b, float* __restrict__ out, int N,
    int bid, int nb, float* Wh, float* Wl)
{
    int t    = threadIdx.x;
    int w    = t >> 5;
    int lane = t & 31;
    int g    = lane >> 2;
    int tg   = lane & 3;
    int rowg = w & 3;
    int c0   = (w >> 2) * 64;

#pragma unroll
    for (int u = 0; u < 4; u++) {
        int fi = u * 256 + t;
        int k = fi >> 5, n0 = (fi & 31) * 4;
        float4 v = *(const float4*)(W + (size_t)k * HD + n0);
        float4 h, l;
        h.x = tf32f(v.x); l.x = tf32f(v.x - h.x);
        h.y = tf32f(v.y); l.y = tf32f(v.y - h.y);
        h.z = tf32f(v.z); l.z = tf32f(v.z - h.z);
        h.w = tf32f(v.w); l.w = tf32f(v.w - h.w);
        *(float4*)(Wh + k * EWST + n0) = h;
        *(float4*)(Wl + k * EWST + n0) = l;
    }
    __syncthreads();

    int ntiles = (N + 63) / 64;
    for (int tile = bid; tile < ntiles; tile += nb) {
        int r0 = tile * 64 + rowg * 16 + g;
        int r1 = r0 + 8;
        const float* xr0 = x + (size_t)r0 * 32 + tg;
        const float* xr1 = x + (size_t)r1 * 32 + tg;
        bool v0 = r0 < N, v1 = r1 < N;

        float a0f[8], a1f[8];
#pragma unroll
        for (int q = 0; q < 8; q++) {
            a0f[q] = v0 ? xr0[q * 4] : 0.f;
            a1f[q] = v1 ? xr1[q * 4] : 0.f;
        }
        unsigned ah0[8], al0[8], ah1[8], al1[8];
#pragma unroll
        for (int q = 0; q < 8; q++) {
            float h0 = tf32f(a0f[q]); ah0[q] = __float_as_uint(h0);
            al0[q] = tf32u(a0f[q] - h0);
            float h1 = tf32f(a1f[q]); ah1[q] = __float_as_uint(h1);
            al1[q] = tf32u(a1f[q] - h1);
        }

        float acc[8][4];
#pragma unroll
        for (int j = 0; j < 8; j++)
#pragma unroll
            for (int q = 0; q < 4; q++) acc[j][q] = 0.f;

#pragma unroll
        for (int kt = 0; kt < 4; kt++) {
            int k0 = kt * 8;
            const float* wh0 = Wh + (k0 + tg) * EWST + c0 + g;
            const float* wh1 = wh0 + 4 * EWST;
            const float* wl0 = Wl + (k0 + tg) * EWST + c0 + g;
            const float* wl1 = wl0 + 4 * EWST;
            unsigned A0h = ah0[kt * 2], A2h = ah0[kt * 2 + 1];
            unsigned A1h = ah1[kt * 2], A3h = ah1[kt * 2 + 1];
            unsigned A0l = al0[kt * 2], A2l = al0[kt * 2 + 1];
            unsigned A1l = al1[kt * 2], A3l = al1[kt * 2 + 1];
#pragma unroll
            for (int j = 0; j < 8; j++) {
                unsigned bh0 = __float_as_uint(wh0[8 * j]);
                unsigned bh1 = __float_as_uint(wh1[8 * j]);
                unsigned bl0 = __float_as_uint(wl0[8 * j]);
                unsigned bl1 = __float_as_uint(wl1[8 * j]);
                mma8(acc[j], A0l, A1l, A2l, A3l, bh0, bh1);
                mma8(acc[j], A0h, A1h, A2h, A3h, bl0, bl1);
                mma8(acc[j], A0h, A1h, A2h, A3h, bh0, bh1);
            }
        }

#pragma unroll
        for (int j = 0; j < 8; j++) {
            int col = c0 + 8 * j + 2 * tg;
            float2 bb = *(const float2*)(b + col);
            if (v0) {
                float2 o;
                o.x = fmaxf(acc[j][0] + bb.x, 0.f);
                o.y = fmaxf(acc[j][1] + bb.y, 0.f);
                *(float2*)(out + (size_t)r0 * HD + col) = o;
            }
            if (v1) {
                float2 o;
                o.x = fmaxf(acc[j][2] + bb.x, 0.f);
                o.y = fmaxf(acc[j][3] + bb.y, 0.f);
                *(float2*)(out + (size_t)r1 * HD + col) = o;
            }
        }
    }
}

__global__ __launch_bounds__(256) void enc_mma_kernel(
    const float* __restrict__ x, const float* __restrict__ W,
    const float* __restrict__ b, float* __restrict__ out, int N)
{
    __shared__ float Wh[32 * EWST];
    __shared__ float Wl[32 * EWST];
    enc_body(x, W, b, out, N, blockIdx.x, gridDim.x, Wh, Wl);
}

// paired encoder: blocks [0,g0) do type A, [g0,g0+g1) do type B
__global__ __launch_bounds__(256) void enc_mma_pair_kernel(
    const float* xA, const float* WA, const float* bA, float* oA, int NA, int g0,
    const float* xB, const float* WB_, const float* bB, float* oB, int NB)
{
    __shared__ float Wh[32 * EWST];
    __shared__ float Wl[32 * EWST];
    if ((int)blockIdx.x < g0)
        enc_body(xA, WA, bA, oA, NA, blockIdx.x, g0, Wh, Wl);
    else
        enc_body(xB, WB_, bB, oB, NB, blockIdx.x - g0, gridDim.x - g0, Wh, Wl);
}

// ---------------- edge scatter: msg[dst[e]] += h_src[src[e]] ---------------
#define EPW 4
__global__ __launch_bounds__(256) void scatter_kernel(
    const float* __restrict__ h_src, const int* __restrict__ src,
    const int* __restrict__ dst, float* __restrict__ msg, int E)
{
    int wid = blockIdx.x * (blockDim.x >> 5) + (threadIdx.x >> 5);
    int lane = threadIdx.x & 31;
    int e0 = wid * EPW;
    if (e0 >= E) return;

    int4 s4, d4;
    if (e0 + EPW <= E) {
        s4 = *(const int4*)(src + e0);
        d4 = *(const int4*)(dst + e0);
    } else {
        s4.x = src[e0];
        s4.y = (e0 + 1 < E) ? src[e0 + 1] : -1;
        s4.z = (e0 + 2 < E) ? src[e0 + 2] : -1;
        s4.w = (e0 + 3 < E) ? src[e0 + 3] : -1;
        d4.x = dst[e0];
        d4.y = (e0 + 1 < E) ? dst[e0 + 1] : 0;
        d4.z = (e0 + 2 < E) ? dst[e0 + 2] : 0;
        d4.w = (e0 + 3 < E) ? dst[e0 + 3] : 0;
    }
    int sidx[EPW] = { s4.x, s4.y, s4.z, s4.w };
    int didx[EPW] = { d4.x, d4.y, d4.z, d4.w };

    float4 v[EPW];
#pragma unroll
    for (int i = 0; i < EPW; i++)
        if (sidx[i] >= 0)
            v[i] = *(const float4*)(h_src + (size_t)sidx[i] * HD + lane * 4);
#pragma unroll
    for (int i = 0; i < EPW; i++)
        if (sidx[i] >= 0)
            atomicAdd((float4*)(msg + (size_t)didx[i] * HD + lane * 4), v[i]);
}

// ------- tree MLP: 32-node tiles, 3 blocks/SM, cp.async W staging ----------
// 256 thr, 8 warps: rowg = w&1 (16 rows), colq = w>>1 (32 cols).
#define BNM   32
#define TPA   260
#define WST   136
#define WCHUNK_F (32 * WST)
#define MLP_SMEM ((BNM * TPA + 2 * WCHUNK_F) * sizeof(float))

__device__ __forceinline__ void stage_async(float* wb, const float* __restrict__ Wr,
                                            int krow0, int t) {
    unsigned dst = (unsigned)__cvta_generic_to_shared(wb);
#pragma unroll
    for (int u = 0; u < 4; u++) {
        int fi = u * 256 + t;
        int k = fi >> 5;
        int n0 = (fi & 31) * 4;
        CP_ASYNC16(dst + (unsigned)(k * WST + n0) * 4,
                   Wr + (size_t)(krow0 + k) * HD + n0);
    }
}

__global__ __launch_bounds__(256) void tree_mlp_mma(
    float* __restrict__ h_dst, float* __restrict__ msg,
    const float* __restrict__ W1r, const float* __restrict__ b1,
    const float* __restrict__ W2r, const float* __restrict__ b2, int N)
{
    extern __shared__ float s[];
    float* A  = s;                       // [BNM][TPA]
    float* WB = s + BNM * TPA;           // [2][32][WST]

    int t    = threadIdx.x;
    int base = blockIdx.x * BNM;
    int w    = t >> 5;
    int lane = t & 31;
    int g    = lane >> 2;
    int tg   = lane & 3;
    int rowg = w & 1;                    // 0..1 -> rows [16*rowg, +16)
    int c0   = (w >> 1) * 32;            // column quarter
    int m0   = rowg * 16;

    // stage A = tf32(concat(h_dst, msg)) : 32 nodes x 256 feats
    for (int i = t; i < BNM * 64; i += 256) {
        int n = i >> 6, q = i & 63;
        int f0 = q * 4;
        float4 v = make_float4(0.f, 0.f, 0.f, 0.f);
        if (base + n < N) {
            if (q < 32) v = *(const float4*)(h_dst + (size_t)(base + n) * HD + f0);
            else        v = *(const float4*)(msg   + (size_t)(base + n) * HD + (f0 - 128));
        }
        v.x = tf32f(v.x); v.y = tf32f(v.y); v.z = tf32f(v.z); v.w = tf32f(v.w);
        *(float4*)(A + n * TPA + f0) = v;
    }
    stage_async(WB, W1r, 0, t);
    CP_COMMIT();
    __syncthreads();          // A visible; all staging reads of msg done

    // re-zero consumed msg rows (after barrier: no thread still reads msg)
    {
        float4 z4 = make_float4(0.f, 0.f, 0.f, 0.f);
        for (int i = t; i < BNM * 32; i += 256) {
            int n = i >> 5, q = i & 31;
            if (base + n < N)
                *(float4*)(msg + (size_t)(base + n) * HD + q * 4) = z4;
        }
    }

    float acc[4][4];
#pragma unroll
    for (int j = 0; j < 4; j++)
#pragma unroll
        for (int q = 0; q < 4; q++) acc[j][q] = 0.f;

    const float* arow0 = A + (m0 + g) * TPA + tg;
    const float* arow1 = arow0 + 8 * TPA;

    // ---- layer 1: 8 chunks of 32 K-rows (K=256) ----
    for (int c = 0; c < 8; c++) {
        CP_WAIT0();
        __syncthreads();
        if (c + 1 < 8) {
            stage_async(WB + ((c + 1) & 1) * WCHUNK_F, W1r, (c + 1) * 32, t);
            CP_COMMIT();
        }
        const float* wb = WB + (c & 1) * WCHUNK_F;
#pragma unroll
        for (int kt = 0; kt < 4; kt++) {
            int k0 = c * 32 + kt * 8;
            unsigned a0 = __float_as_uint(arow0[k0]);
            unsigned a1 = __float_as_uint(arow1[k0]);
            unsigned a2 = __float_as_uint(arow0[k0 + 4]);
            unsigned a3 = __float_as_uint(arow1[k0 + 4]);
            const float* wrow0 = wb + (kt * 8 + tg) * WST + c0 + g;
            const float* wrow1 = wrow0 + 4 * WST;
#pragma unroll
            for (int j = 0; j < 4; j++) {
                unsigned b0 = __float_as_uint(wrow0[8 * j]);
                unsigned b1v = __float_as_uint(wrow1[8 * j]);
                mma8(acc[j], a0, a1, a2, a3, b0, b1v);
            }
        }
    }
    __syncthreads();          // all layer-1 reads of A done before Z overwrite

    // ---- bias + relu + write Z (tf32) into A cols [0,128) ----
    {
        float* zr0 = A + (m0 + g) * TPA;
        float* zr1 = zr0 + 8 * TPA;
#pragma unroll
        for (int j = 0; j < 4; j++) {
            int col = c0 + 8 * j + 2 * tg;
            float2 bb = *(const float2*)(b1 + col);
            float2 z0, z1;
            z0.x = tf32f(fmaxf(acc[j][0] + bb.x, 0.f));
            z0.y = tf32f(fmaxf(acc[j][1] + bb.y, 0.f));
            z1.x = tf32f(fmaxf(acc[j][2] + bb.x, 0.f));
            z1.y = tf32f(fmaxf(acc[j][3] + bb.y, 0.f));
            *(float2*)(zr0 + col) = z0;
            *(float2*)(zr1 + col) = z1;
            acc[j][0] = acc[j][1] = acc[j][2] = acc[j][3] = 0.f;
        }
    }
    stage_async(WB, W2r, 0, t);
    CP_COMMIT();

    // ---- layer 2: 4 chunks of 32 K-rows (K=128) ----
    for (int c = 0; c < 4; c++) {
        CP_WAIT0();
        __syncthreads();      // also orders Z writes before first compute
        if (c + 1 < 4) {
            stage_async(WB + ((c + 1) & 1) * WCHUNK_F, W2r, (c + 1) * 32, t);
            CP_COMMIT();
        }
        const float* wb = WB + (c & 1) * WCHUNK_F;
#pragma unroll
        for (int kt = 0; kt < 4; kt++) {
            int k0 = c * 32 + kt * 8;
            unsigned a0 = __float_as_uint(arow0[k0]);
            unsigned a1 = __float_as_uint(arow1[k0]);
            unsigned a2 = __float_as_uint(arow0[k0 + 4]);
            unsigned a3 = __float_as_uint(arow1[k0 + 4]);
            const float* wrow0 = wb + (kt * 8 + tg) * WST + c0 + g;
            const float* wrow1 = wrow0 + 4 * WST;
#pragma unroll
            for (int j = 0; j < 4; j++) {
                unsigned b0 = __float_as_uint(wrow0[8 * j]);
                unsigned b1v = __float_as_uint(wrow1[8 * j]);
                mma8(acc[j], a0, a1, a2, a3, b0, b1v);
            }
        }
    }

    // ---- bias + relu + store to gmem ----
    {
        int n0g = base + m0 + g;
        int n1g = n0g + 8;
#pragma unroll
        for (int j = 0; j < 4; j++) {
            int col = c0 + 8 * j + 2 * tg;
            float2 bb = *(const float2*)(b2 + col);
            if (n0g < N) {
                float2 o;
                o.x = fmaxf(acc[j][0] + bb.x, 0.f);
                o.y = fmaxf(acc[j][1] + bb.y, 0.f);
                *(float2*)(h_dst + (size_t)n0g * HD + col) = o;
            }
            if (n1g < N) {
                float2 o;
                o.x = fmaxf(acc[j][2] + bb.x, 0.f);
                o.y = fmaxf(acc[j][3] + bb.y, 0.f);
                *(float2*)(h_dst + (size_t)n1g * HD + col) = o;
            }
        }
    }
}

// ------- head: out[n] = relu(h @ Wf1 + bf1) @ Wf2 + bf2 --------------------
__global__ __launch_bounds__(128) void final_kernel(
    const float* __restrict__ h, const float* __restrict__ Wf1,
    const float* __restrict__ bf1, const float* __restrict__ Wf2,
    const float* __restrict__ bf2, float* __restrict__ out, int N)
{
    const int BN = 16;
    __shared__ float s_in[BN][128];
    __shared__ float s_z[BN][129];
    int base = blockIdx.x * BN;
    int t = threadIdx.x;

    for (int i = t; i < BN * 32; i += 128) {
        int n = i >> 5, c4 = (i & 31) * 4;
        float4 a = make_float4(0.f, 0.f, 0.f, 0.f);
        if (base + n < N) a = *(const float4*)(h + (size_t)(base + n) * HD + c4);
        *(float4*)&s_in[n][c4] = a;
    }
    __syncthreads();

    float acc[BN];
    float bb = bf1[t];
#pragma unroll
    for (int n = 0; n < BN; n++) acc[n] = bb;
#pragma unroll 4
    for (int k0 = 0; k0 < 128; k0 += 4) {
        float w0 = Wf1[(k0 + 0) * HD + t];
        float w1 = Wf1[(k0 + 1) * HD + t];
        float w2 = Wf1[(k0 + 2) * HD + t];
        float w3 = Wf1[(k0 + 3) * HD + t];
#pragma unroll
        for (int n = 0; n < BN; n++) {
            float4 sv = *(const float4*)&s_in[n][k0];
            acc[n] = fmaf(sv.x, w0, acc[n]);
            acc[n] = fmaf(sv.y, w1, acc[n]);
            acc[n] = fmaf(sv.z, w2, acc[n]);
            acc[n] = fmaf(sv.w, w3, acc[n]);
        }
    }
#pragma unroll
    for (int n = 0; n < BN; n++) s_z[n][t] = fmaxf(acc[n], 0.f);
    __syncthreads();

    if (t < BN && base + t < N) {
        float a = bf2[0];
#pragma unroll 4
        for (int k = 0; k < 128; k++) a = fmaf(s_z[t][k], Wf2[k], a);
        out[base + t] = a;
    }
}

// ---------------------------------------------------------------------------
extern "C" void kernel_launch(void* const* d_in, const int* in_sizes, int n_in,
                              void* d_out, int out_size)
{
    const float* xs[6] = {
        (const float*)d_in[0], (const float*)d_in[1], (const float*)d_in[2],
        (const float*)d_in[3], (const float*)d_in[4], (const float*)d_in[5]
    };
    const float* W_enc = (const float*)d_in[6];
    const float* b_enc = (const float*)d_in[7];
    const float* W1    = (const float*)d_in[8];
    const float* b1    = (const float*)d_in[9];
    const float* W2    = (const float*)d_in[10];
    const float* b2    = (const float*)d_in[11];
    const float* Wf1   = (const float*)d_in[12];
    const float* bf1   = (const float*)d_in[13];
    const float* Wf2   = (const float*)d_in[14];
    const float* bf2   = (const float*)d_in[15];
    const int* esrc[5] = { (const int*)d_in[16], (const int*)d_in[18],
                           (const int*)d_in[20], (const int*)d_in[22],
                           (const int*)d_in[24] };
    const int* edst[5] = { (const int*)d_in[17], (const int*)d_in[19],
                           (const int*)d_in[21], (const int*)d_in[23],
                           (const int*)d_in[25] };
    int E[5] = { in_sizes[16], in_sizes[18], in_sizes[20], in_sizes[22], in_sizes[24] };
    int Nn[6];
    for (int i = 0; i < 6; i++) Nn[i] = in_sizes[i] / 32;

    float *hb[6], *msg, *w1r, *w2r;
    cudaGetSymbolAddress((void**)&hb[0], g_hcol);
    cudaGetSymbolAddress((void**)&hb[1], g_hfilt);
    cudaGetSymbolAddress((void**)&hb[2], g_hpred);
    cudaGetSymbolAddress((void**)&hb[3], g_hscan);
    cudaGetSymbolAddress((void**)&hb[4], g_hjoin);
    cudaGetSymbolAddress((void**)&hb[5], g_henc);
    cudaGetSymbolAddress((void**)&msg,   g_msg);
    cudaGetSymbolAddress((void**)&w1r,   g_w1r);
    cudaGetSymbolAddress((void**)&w2r,   g_w2r);

    cudaFuncSetAttribute(tree_mlp_mma,
                         cudaFuncAttributeMaxDynamicSharedMemorySize, (int)MLP_SMEM);

    cudaMemsetAsync(msg, 0, (size_t)MSGCAP * HD * sizeof(float));

    auto scat = [&](int l) {
        int nwarp = (E[l] + EPW - 1) / EPW;
        int sgrid = (nwarp + 7) / 8;
        scatter_kernel<<<sgrid, 256>>>(hb[l], esrc[l], edst[l], msg, E[l]);
    };
    auto mlp = [&](int l) {
        int Ndst = Nn[l + 1];
        int mgrid = (Ndst + BNM - 1) / BNM;
        tree_mlp_mma<<<mgrid, 256, MLP_SMEM>>>(hb[l + 1], msg,
                                        w1r + (size_t)l * 256 * HD, b1 + (size_t)l * HD,
                                        w2r + (size_t)l * HD * HD,  b2 + (size_t)l * HD,
                                        Ndst);
    };
    auto enc = [&](int i) {
        int ntiles = (Nn[i] + 63) / 64;
        int grid = ntiles < 296 ? ntiles : 296;
        enc_mma_kernel<<<grid, 256>>>(xs[i], W_enc + (size_t)i * 32 * HD,
                                      b_enc + (size_t)i * HD, hb[i], Nn[i]);
    };

    // kernel launch order (ncu profiles 4th kernel = mlp0):
    w_prep_kernel<<<640, 256>>>(W1, W2);                     // 1
    {   // 2: paired encoder for types 0 and 1
        int t0 = (Nn[0] + 63) / 64; int g0 = t0 < 296 ? t0 : 296;
        int t1 = (Nn[1] + 63) / 64; int g1 = t1 < 296 ? t1 : 296;
        enc_mma_pair_kernel<<<g0 + g1, 256>>>(
            xs[0], W_enc + 0 * 32 * HD, b_enc + 0 * HD, hb[0], Nn[0], g0,
            xs[1], W_enc + 1 * 32 * HD, b_enc + 1 * HD, hb[1], Nn[1]);
    }
    scat(0);           // 3  (needs enc0)
    mlp(0);            // 4  <- profiled (needs enc1 + scat0 + prep)
    enc(2);            // 5
    scat(1);           // 6  (needs mlp0)
    mlp(1);            // 7
    enc(3);            // 8
    scat(2);           // 9
    mlp(2);            // 10
    enc(4);            // 11
    scat(3);           // 12
    mlp(3);            // 13
    enc(5);            // 14
    scat(4);           // 15
    mlp(4);            // 16

    {
        int grid = (Nn[5] + 15) / 16;
        final_kernel<<<grid, 128>>>(hb[5], Wf1, bf1, Wf2, bf2, (float*)d_out, Nn[5]);
    }
}